// round 1
// baseline (speedup 1.0000x reference)
#include <cuda_runtime.h>
#include <math.h>

#define QL 2048
#define CL 2048
#define HD 1024
#define NH 16
#define DH 64
#define FF 4096
#define RL 4096

// ---------------- scratch (static device allocations; no cudaMalloc) ----------
__device__ float g_q[QL * HD];
__device__ float g_k[CL * HD];
__device__ float g_v[CL * HD];
__device__ float g_r[RL * HD];
__device__ float g_scores[(size_t)NH * QL * CL];   // 256 MB
__device__ float g_eseg[2 * NH * QL];
__device__ float g_attn[QL * HD];
__device__ float g_attnout[QL * HD];
__device__ float g_ffnin[QL * HD];
__device__ float g_ffnh[QL * FF];
__device__ float g_ffnout[QL * HD];

__device__ __forceinline__ float warpSum(float v) {
#pragma unroll
    for (int o = 16; o; o >>= 1) v += __shfl_xor_sync(0xffffffffu, v, o);
    return v;
}
__device__ __forceinline__ float warpMax(float v) {
#pragma unroll
    for (int o = 16; o; o >>= 1) v = fmaxf(v, __shfl_xor_sync(0xffffffffu, v, o));
    return v;
}

// ---------------- generic tiled SGEMM: C = A @ B (or A @ B^T), fp32 ----------
// 64x64 tile, BK=16, 256 threads, 4x4 per thread. Requires M%64==0, N%64==0, K%16==0.
template <bool TB>
__global__ void __launch_bounds__(256) sgemm_kernel(
    const float* __restrict__ A, const float* __restrict__ B, float* __restrict__ C,
    int M, int N, int K, int lda, int ldb, int ldc,
    long long sA, long long sB, long long sC,
    const float* __restrict__ bias, int relu)
{
    A += (long long)blockIdx.z * sA;
    B += (long long)blockIdx.z * sB;
    C += (long long)blockIdx.z * sC;

    __shared__ float As[64][17];
    __shared__ float Bs[16][64];

    const int tid = threadIdx.x;
    const int tx = tid & 15, ty = tid >> 4;
    const int m0 = blockIdx.y * 64, n0 = blockIdx.x * 64;

    float acc[4][4] = {};

    const int am = tid >> 2;            // 0..63
    const int akb = (tid & 3) << 2;     // 0,4,8,12

    for (int k0 = 0; k0 < K; k0 += 16) {
        // load A tile (64x16)
        {
            float4 a4 = *(const float4*)(A + (long long)(m0 + am) * lda + (k0 + akb));
            As[am][akb + 0] = a4.x; As[am][akb + 1] = a4.y;
            As[am][akb + 2] = a4.z; As[am][akb + 3] = a4.w;
        }
        // load B tile (16x64)
        if (!TB) {
            int kk = tid >> 4, nb = (tid & 15) << 2;
            float4 b4 = *(const float4*)(B + (long long)(k0 + kk) * ldb + (n0 + nb));
            *(float4*)&Bs[kk][nb] = b4;
        } else {
            int nn = tid >> 2, kb = (tid & 3) << 2;
            float4 b4 = *(const float4*)(B + (long long)(n0 + nn) * ldb + (k0 + kb));
            Bs[kb + 0][nn] = b4.x; Bs[kb + 1][nn] = b4.y;
            Bs[kb + 2][nn] = b4.z; Bs[kb + 3][nn] = b4.w;
        }
        __syncthreads();

#pragma unroll
        for (int k = 0; k < 16; k++) {
            float a0 = As[ty * 4 + 0][k];
            float a1 = As[ty * 4 + 1][k];
            float a2 = As[ty * 4 + 2][k];
            float a3 = As[ty * 4 + 3][k];
            float4 b4 = *(const float4*)&Bs[k][tx * 4];
            acc[0][0] += a0 * b4.x; acc[0][1] += a0 * b4.y; acc[0][2] += a0 * b4.z; acc[0][3] += a0 * b4.w;
            acc[1][0] += a1 * b4.x; acc[1][1] += a1 * b4.y; acc[1][2] += a1 * b4.z; acc[1][3] += a1 * b4.w;
            acc[2][0] += a2 * b4.x; acc[2][1] += a2 * b4.y; acc[2][2] += a2 * b4.z; acc[2][3] += a2 * b4.w;
            acc[3][0] += a3 * b4.x; acc[3][1] += a3 * b4.y; acc[3][2] += a3 * b4.z; acc[3][3] += a3 * b4.w;
        }
        __syncthreads();
    }

    float bb[4] = {0.f, 0.f, 0.f, 0.f};
    if (bias) {
#pragma unroll
        for (int v = 0; v < 4; v++) bb[v] = bias[n0 + tx * 4 + v];
    }
#pragma unroll
    for (int u = 0; u < 4; u++) {
        float4 o;
        o.x = acc[u][0] + bb[0];
        o.y = acc[u][1] + bb[1];
        o.z = acc[u][2] + bb[2];
        o.w = acc[u][3] + bb[3];
        if (relu) {
            o.x = fmaxf(o.x, 0.f); o.y = fmaxf(o.y, 0.f);
            o.z = fmaxf(o.z, 0.f); o.w = fmaxf(o.w, 0.f);
        }
        *(float4*)(C + (long long)(m0 + ty * 4 + u) * ldc + (n0 + tx * 4)) = o;
    }
}

// ---------------- segment-bias dots: e[s][n][qi] = (q + sb) . seg[s] ----------
__global__ void __launch_bounds__(256) eseg_kernel(
    const float* __restrict__ sb, const float* __restrict__ seg)
{
    int idx = blockIdx.x * 256 + threadIdx.x;           // 2*NH*QL = 65536
    if (idx >= 2 * NH * QL) return;
    int s = idx / (NH * QL);
    int n = (idx / QL) % NH;
    int qi = idx % QL;
    const float* qr = g_q + (long long)qi * HD + n * DH;
    const float* sbr = sb + n * DH;
    const float* sg = seg + s * (NH * DH) + n * DH;
    float acc = 0.f;
#pragma unroll
    for (int d = 0; d < DH; d++) acc += (qr[d] + sbr[d]) * sg[d];
    g_eseg[idx] = acc;
}

// ---------------- fused score kernel: ac + rel-shifted bd + ef + mask ---------
// scores[n][qi][ci] = ((q+cb).k[ci] + (q+pb).r[ci+QL-qi] + e[seg]) / 8 - 1e30*mask
__global__ void __launch_bounds__(256) score_kernel(
    const float* __restrict__ mask, const unsigned char* __restrict__ segmat,
    const float* __restrict__ cb, const float* __restrict__ pb)
{
    const int n = blockIdx.z;
    const int q0 = blockIdx.y * 16;
    const int c0 = blockIdx.x * 16;

    __shared__ float qc[16][64];
    __shared__ float qp[16][64];
    __shared__ float kt[16][65];
    __shared__ float rb[31][65];

    const int tid = threadIdx.x;
    for (int i = tid; i < 16 * 64; i += 256) {
        int row = i >> 6, d = i & 63;
        float qv = g_q[(long long)(q0 + row) * HD + n * DH + d];
        qc[row][d] = qv + cb[n * DH + d];
        qp[row][d] = qv + pb[n * DH + d];
        kt[row][d] = g_k[(long long)(c0 + row) * HD + n * DH + d];
    }
    const int rbase = c0 - q0 + QL - 15;   // in [1, 4065]
    for (int i = tid; i < 31 * 64; i += 256) {
        int row = i >> 6, d = i & 63;
        rb[row][d] = g_r[(long long)(rbase + row) * HD + n * DH + d];
    }
    __syncthreads();

    const int tx = tid & 15, ty = tid >> 4;
    const int roff = tx - ty + 15;   // 0..30
    float ac = 0.f, bd = 0.f;
#pragma unroll
    for (int d = 0; d < 64; d++) {
        ac += qc[ty][d] * kt[tx][d];
        bd += qp[ty][d] * rb[roff][d];
    }
    const int qi = q0 + ty, ci = c0 + tx;
    const size_t mi = (size_t)qi * CL + ci;
    float e = segmat[mi] ? g_eseg[(1 * NH + n) * QL + qi]
                         : g_eseg[(0 * NH + n) * QL + qi];
    float s = (ac + bd + e) * 0.125f - 1e30f * mask[mi];
    g_scores[((size_t)n * QL + qi) * CL + ci] = s;
}

// ---------------- row softmax over 2048 keys --------------------------------
__global__ void __launch_bounds__(256) softmax_kernel()
{
    const size_t row = blockIdx.x;           // n*QL + qi
    float* p = g_scores + row * (size_t)CL;
    const int tid = threadIdx.x;
    __shared__ float red[8];
    __shared__ float sh;

    float v[8];
    float mx = -3.4e38f;
#pragma unroll
    for (int j = 0; j < 8; j++) { v[j] = p[tid + 256 * j]; mx = fmaxf(mx, v[j]); }
    mx = warpMax(mx);
    if ((tid & 31) == 0) red[tid >> 5] = mx;
    __syncthreads();
    if (tid == 0) {
        float m = red[0];
#pragma unroll
        for (int i = 1; i < 8; i++) m = fmaxf(m, red[i]);
        sh = m;
    }
    __syncthreads();
    mx = sh;

    float sum = 0.f;
#pragma unroll
    for (int j = 0; j < 8; j++) { v[j] = __expf(v[j] - mx); sum += v[j]; }
    sum = warpSum(sum);
    __syncthreads();
    if ((tid & 31) == 0) red[tid >> 5] = sum;
    __syncthreads();
    if (tid == 0) {
        float s = 0.f;
#pragma unroll
        for (int i = 0; i < 8; i++) s += red[i];
        sh = 1.0f / s;
    }
    __syncthreads();
    const float inv = sh;
#pragma unroll
    for (int j = 0; j < 8; j++) p[tid + 256 * j] = v[j] * inv;
}

// ---------------- residual add + LayerNorm ----------------------------------
__global__ void __launch_bounds__(256) ln_kernel(
    const float* __restrict__ x, const float* __restrict__ res,
    const float* __restrict__ g, const float* __restrict__ b,
    float* __restrict__ out)
{
    const int row = blockIdx.x;
    __shared__ float buf[HD];
    __shared__ float red[8];
    __shared__ float s_mean, s_rstd;
    const int tid = threadIdx.x;

    float lsum = 0.f;
    for (int i = tid; i < HD; i += 256) {
        float v = x[(long long)row * HD + i] + res[(long long)row * HD + i];
        buf[i] = v;
        lsum += v;
    }
    lsum = warpSum(lsum);
    if ((tid & 31) == 0) red[tid >> 5] = lsum;
    __syncthreads();
    if (tid == 0) {
        float s = 0.f;
#pragma unroll
        for (int i = 0; i < 8; i++) s += red[i];
        s_mean = s * (1.0f / HD);
    }
    __syncthreads();
    const float m = s_mean;

    float lv = 0.f;
    for (int i = tid; i < HD; i += 256) { float d = buf[i] - m; lv += d * d; }
    lv = warpSum(lv);
    __syncthreads();
    if ((tid & 31) == 0) red[tid >> 5] = lv;
    __syncthreads();
    if (tid == 0) {
        float s = 0.f;
#pragma unroll
        for (int i = 0; i < 8; i++) s += red[i];
        s_rstd = rsqrtf(s * (1.0f / HD) + 1e-12f);
    }
    __syncthreads();
    const float rs = s_rstd;
    for (int i = tid; i < HD; i += 256)
        out[(long long)row * HD + i] = (buf[i] - m) * rs * g[i] + b[i];
}

// ---------------- launch ------------------------------------------------------
extern "C" void kernel_launch(void* const* d_in, const int* in_sizes, int n_in,
                              void* d_out, int out_size)
{
    const float* cs   = (const float*)d_in[0];   // content_stream (Q,H)
    const float* mask = (const float*)d_in[1];   // content_mask (Q,C)
    const float* ctx  = (const float*)d_in[2];   // context (C,H)
    const float* pos  = (const float*)d_in[3];   // position_encoding (R,H)
    const float* cb   = (const float*)d_in[4];   // content_bias (N,D)
    const float* pb   = (const float*)d_in[5];   // position_bias (N,D)
    const float* seg  = (const float*)d_in[6];   // segment_encoding (2,N,D)
    const unsigned char* segm = (const unsigned char*)d_in[7]; // segment_matrix bool
    const float* sb   = (const float*)d_in[8];   // segment_bias (N,D)
    const float* Wq   = (const float*)d_in[9];
    const float* Wk   = (const float*)d_in[10];
    const float* Wv   = (const float*)d_in[11];
    const float* Wr   = (const float*)d_in[12];
    const float* Wo   = (const float*)d_in[13];
    const float* g1   = (const float*)d_in[14];
    const float* be1  = (const float*)d_in[15];
    const float* W1   = (const float*)d_in[16];
    const float* bf1  = (const float*)d_in[17];
    const float* W2   = (const float*)d_in[18];
    const float* bf2  = (const float*)d_in[19];
    const float* g2   = (const float*)d_in[20];
    const float* be2  = (const float*)d_in[21];
    float* out = (float*)d_out;

    float *pq, *pk, *pv, *pr, *psc, *pattn, *pao, *pfi, *pfh, *pfo;
    cudaGetSymbolAddress((void**)&pq,    g_q);
    cudaGetSymbolAddress((void**)&pk,    g_k);
    cudaGetSymbolAddress((void**)&pv,    g_v);
    cudaGetSymbolAddress((void**)&pr,    g_r);
    cudaGetSymbolAddress((void**)&psc,   g_scores);
    cudaGetSymbolAddress((void**)&pattn, g_attn);
    cudaGetSymbolAddress((void**)&pao,   g_attnout);
    cudaGetSymbolAddress((void**)&pfi,   g_ffnin);
    cudaGetSymbolAddress((void**)&pfh,   g_ffnh);
    cudaGetSymbolAddress((void**)&pfo,   g_ffnout);

    dim3 blk(256);

    // projections: X @ W  (W is [H, N*D] row-major)
    sgemm_kernel<false><<<dim3(HD / 64, QL / 64, 1), blk>>>(cs,  Wq, pq, QL, HD, HD, HD, HD, HD, 0, 0, 0, nullptr, 0);
    sgemm_kernel<false><<<dim3(HD / 64, CL / 64, 1), blk>>>(ctx, Wk, pk, CL, HD, HD, HD, HD, HD, 0, 0, 0, nullptr, 0);
    sgemm_kernel<false><<<dim3(HD / 64, CL / 64, 1), blk>>>(ctx, Wv, pv, CL, HD, HD, HD, HD, HD, 0, 0, 0, nullptr, 0);
    sgemm_kernel<false><<<dim3(HD / 64, RL / 64, 1), blk>>>(pos, Wr, pr, RL, HD, HD, HD, HD, HD, 0, 0, 0, nullptr, 0);

    // segment-bias dot products
    eseg_kernel<<<(2 * NH * QL) / 256, blk>>>(sb, seg);

    // fused relative-attention scores
    score_kernel<<<dim3(CL / 16, QL / 16, NH), blk>>>(mask, segm, cb, pb);

    // softmax rows
    softmax_kernel<<<NH * QL, blk>>>();

    // attn = probs @ v (per head, batched over z)
    sgemm_kernel<false><<<dim3(1, QL / 64, NH), blk>>>(
        psc, pv, pattn, QL, 64, CL, CL, HD, HD,
        (long long)QL * CL, 64, 64, nullptr, 0);

    // attn_out = attn @ Wo^T  (Wo is [H, N*D]; contract over N*D)
    sgemm_kernel<true><<<dim3(HD / 64, QL / 64, 1), blk>>>(
        pattn, Wo, pao, QL, HD, HD, HD, HD, HD, 0, 0, 0, nullptr, 0);

    // LN1(attn_out + content_stream) -> ffn_in
    ln_kernel<<<QL, blk>>>(pao, cs, g1, be1, pfi);

    // FFN
    sgemm_kernel<false><<<dim3(FF / 64, QL / 64, 1), blk>>>(
        pfi, W1, pfh, QL, FF, HD, HD, FF, FF, 0, 0, 0, bf1, 1);
    sgemm_kernel<false><<<dim3(HD / 64, QL / 64, 1), blk>>>(
        pfh, W2, pfo, QL, HD, FF, FF, HD, HD, 0, 0, 0, bf2, 0);

    // LN2(ffn_out + ffn_in) -> output
    ln_kernel<<<QL, blk>>>(pfo, pfi, g2, be2, out);
}

// round 2
// speedup vs baseline: 1.0017x; 1.0017x over previous
#include <cuda_runtime.h>
#include <math.h>

#define QL 2048
#define CL 2048
#define HD 1024
#define NH 16
#define DH 64
#define FF 4096
#define RL 4096

// ---------------- scratch (static device allocations; no cudaMalloc) ----------
__device__ float g_q[QL * HD];
__device__ float g_k[CL * HD];
__device__ float g_v[CL * HD];
__device__ float g_r[RL * HD];
__device__ float g_scores[(size_t)NH * QL * CL];   // 256 MB
__device__ float g_eseg[2 * NH * QL];
__device__ float g_attn[QL * HD];
__device__ float g_attnout[QL * HD];
__device__ float g_ffnin[QL * HD];
__device__ float g_ffnh[QL * FF];
__device__ float g_ffnout[QL * HD];

__device__ __forceinline__ float warpSum(float v) {
#pragma unroll
    for (int o = 16; o; o >>= 1) v += __shfl_xor_sync(0xffffffffu, v, o);
    return v;
}
__device__ __forceinline__ float warpMax(float v) {
#pragma unroll
    for (int o = 16; o; o >>= 1) v = fmaxf(v, __shfl_xor_sync(0xffffffffu, v, o));
    return v;
}

// ---------------- generic tiled SGEMM: C = A @ B (or A @ B^T), fp32 ----------
// 64x64 tile, BK=16, 256 threads, 4x4 per thread. Requires M%64==0, N%64==0, K%16==0.
template <bool TB>
__global__ void __launch_bounds__(256) sgemm_kernel(
    const float* __restrict__ A, const float* __restrict__ B, float* __restrict__ C,
    int M, int N, int K, int lda, int ldb, int ldc,
    long long sA, long long sB, long long sC,
    const float* __restrict__ bias, int relu)
{
    A += (long long)blockIdx.z * sA;
    B += (long long)blockIdx.z * sB;
    C += (long long)blockIdx.z * sC;

    __shared__ float As[64][17];
    __shared__ float Bs[16][64];

    const int tid = threadIdx.x;
    const int tx = tid & 15, ty = tid >> 4;
    const int m0 = blockIdx.y * 64, n0 = blockIdx.x * 64;

    float acc[4][4] = {};

    const int am = tid >> 2;            // 0..63
    const int akb = (tid & 3) << 2;     // 0,4,8,12

    for (int k0 = 0; k0 < K; k0 += 16) {
        // load A tile (64x16)
        {
            float4 a4 = *(const float4*)(A + (long long)(m0 + am) * lda + (k0 + akb));
            As[am][akb + 0] = a4.x; As[am][akb + 1] = a4.y;
            As[am][akb + 2] = a4.z; As[am][akb + 3] = a4.w;
        }
        // load B tile (16x64)
        if (!TB) {
            int kk = tid >> 4, nb = (tid & 15) << 2;
            float4 b4 = *(const float4*)(B + (long long)(k0 + kk) * ldb + (n0 + nb));
            *(float4*)&Bs[kk][nb] = b4;
        } else {
            int nn = tid >> 2, kb = (tid & 3) << 2;
            float4 b4 = *(const float4*)(B + (long long)(n0 + nn) * ldb + (k0 + kb));
            Bs[kb + 0][nn] = b4.x; Bs[kb + 1][nn] = b4.y;
            Bs[kb + 2][nn] = b4.z; Bs[kb + 3][nn] = b4.w;
        }
        __syncthreads();

#pragma unroll
        for (int k = 0; k < 16; k++) {
            float a0 = As[ty * 4 + 0][k];
            float a1 = As[ty * 4 + 1][k];
            float a2 = As[ty * 4 + 2][k];
            float a3 = As[ty * 4 + 3][k];
            float4 b4 = *(const float4*)&Bs[k][tx * 4];
            acc[0][0] += a0 * b4.x; acc[0][1] += a0 * b4.y; acc[0][2] += a0 * b4.z; acc[0][3] += a0 * b4.w;
            acc[1][0] += a1 * b4.x; acc[1][1] += a1 * b4.y; acc[1][2] += a1 * b4.z; acc[1][3] += a1 * b4.w;
            acc[2][0] += a2 * b4.x; acc[2][1] += a2 * b4.y; acc[2][2] += a2 * b4.z; acc[2][3] += a2 * b4.w;
            acc[3][0] += a3 * b4.x; acc[3][1] += a3 * b4.y; acc[3][2] += a3 * b4.z; acc[3][3] += a3 * b4.w;
        }
        __syncthreads();
    }

    float bb[4] = {0.f, 0.f, 0.f, 0.f};
    if (bias) {
#pragma unroll
        for (int v = 0; v < 4; v++) bb[v] = bias[n0 + tx * 4 + v];
    }
#pragma unroll
    for (int u = 0; u < 4; u++) {
        float4 o;
        o.x = acc[u][0] + bb[0];
        o.y = acc[u][1] + bb[1];
        o.z = acc[u][2] + bb[2];
        o.w = acc[u][3] + bb[3];
        if (relu) {
            o.x = fmaxf(o.x, 0.f); o.y = fmaxf(o.y, 0.f);
            o.z = fmaxf(o.z, 0.f); o.w = fmaxf(o.w, 0.f);
        }
        *(float4*)(C + (long long)(m0 + ty * 4 + u) * ldc + (n0 + tx * 4)) = o;
    }
}

// ---------------- segment-bias dots: e[s][n][qi] = (q + sb) . seg[s] ----------
__global__ void __launch_bounds__(256) eseg_kernel(
    const float* __restrict__ sb, const float* __restrict__ seg)
{
    int idx = blockIdx.x * 256 + threadIdx.x;           // 2*NH*QL = 65536
    if (idx >= 2 * NH * QL) return;
    int s = idx / (NH * QL);
    int n = (idx / QL) % NH;
    int qi = idx % QL;
    const float* qr = g_q + (long long)qi * HD + n * DH;
    const float* sbr = sb + n * DH;
    const float* sg = seg + s * (NH * DH) + n * DH;
    float acc = 0.f;
#pragma unroll
    for (int d = 0; d < DH; d++) acc += (qr[d] + sbr[d]) * sg[d];
    g_eseg[idx] = acc;
}

// ---------------- fused score kernel: ac + rel-shifted bd + ef + mask ---------
// scores[n][qi][ci] = ((q+cb).k[ci] + (q+pb).r[ci+QL-qi] + e[seg]) / 8 - 1e30*mask
__global__ void __launch_bounds__(256) score_kernel(
    const float* __restrict__ mask, const unsigned char* __restrict__ segmat,
    const float* __restrict__ cb, const float* __restrict__ pb)
{
    const int n = blockIdx.z;
    const int q0 = blockIdx.y * 16;
    const int c0 = blockIdx.x * 16;

    __shared__ float qc[16][64];
    __shared__ float qp[16][64];
    __shared__ float kt[16][65];
    __shared__ float rb[31][65];

    const int tid = threadIdx.x;
    for (int i = tid; i < 16 * 64; i += 256) {
        int row = i >> 6, d = i & 63;
        float qv = g_q[(long long)(q0 + row) * HD + n * DH + d];
        qc[row][d] = qv + cb[n * DH + d];
        qp[row][d] = qv + pb[n * DH + d];
        kt[row][d] = g_k[(long long)(c0 + row) * HD + n * DH + d];
    }
    const int rbase = c0 - q0 + QL - 15;   // in [1, 4065]
    for (int i = tid; i < 31 * 64; i += 256) {
        int row = i >> 6, d = i & 63;
        rb[row][d] = g_r[(long long)(rbase + row) * HD + n * DH + d];
    }
    __syncthreads();

    const int tx = tid & 15, ty = tid >> 4;
    const int roff = tx - ty + 15;   // 0..30
    float ac = 0.f, bd = 0.f;
#pragma unroll
    for (int d = 0; d < 64; d++) {
        ac += qc[ty][d] * kt[tx][d];
        bd += qp[ty][d] * rb[roff][d];
    }
    const int qi = q0 + ty, ci = c0 + tx;
    const size_t mi = (size_t)qi * CL + ci;
    float e = segmat[mi] ? g_eseg[(1 * NH + n) * QL + qi]
                         : g_eseg[(0 * NH + n) * QL + qi];
    float s = (ac + bd + e) * 0.125f - 1e30f * mask[mi];
    g_scores[((size_t)n * QL + qi) * CL + ci] = s;
}

// ---------------- row softmax over 2048 keys --------------------------------
__global__ void __launch_bounds__(256) softmax_kernel()
{
    const size_t row = blockIdx.x;           // n*QL + qi
    float* p = g_scores + row * (size_t)CL;
    const int tid = threadIdx.x;
    __shared__ float red[8];
    __shared__ float sh;

    float v[8];
    float mx = -3.4e38f;
#pragma unroll
    for (int j = 0; j < 8; j++) { v[j] = p[tid + 256 * j]; mx = fmaxf(mx, v[j]); }
    mx = warpMax(mx);
    if ((tid & 31) == 0) red[tid >> 5] = mx;
    __syncthreads();
    if (tid == 0) {
        float m = red[0];
#pragma unroll
        for (int i = 1; i < 8; i++) m = fmaxf(m, red[i]);
        sh = m;
    }
    __syncthreads();
    mx = sh;

    float sum = 0.f;
#pragma unroll
    for (int j = 0; j < 8; j++) { v[j] = __expf(v[j] - mx); sum += v[j]; }
    sum = warpSum(sum);
    __syncthreads();
    if ((tid & 31) == 0) red[tid >> 5] = sum;
    __syncthreads();
    if (tid == 0) {
        float s = 0.f;
#pragma unroll
        for (int i = 0; i < 8; i++) s += red[i];
        sh = 1.0f / s;
    }
    __syncthreads();
    const float inv = sh;
#pragma unroll
    for (int j = 0; j < 8; j++) p[tid + 256 * j] = v[j] * inv;
}

// ---------------- residual add + LayerNorm ----------------------------------
__global__ void __launch_bounds__(256) ln_kernel(
    const float* __restrict__ x, const float* __restrict__ res,
    const float* __restrict__ g, const float* __restrict__ b,
    float* __restrict__ out)
{
    const int row = blockIdx.x;
    __shared__ float buf[HD];
    __shared__ float red[8];
    __shared__ float s_mean, s_rstd;
    const int tid = threadIdx.x;

    float lsum = 0.f;
    for (int i = tid; i < HD; i += 256) {
        float v = x[(long long)row * HD + i] + res[(long long)row * HD + i];
        buf[i] = v;
        lsum += v;
    }
    lsum = warpSum(lsum);
    if ((tid & 31) == 0) red[tid >> 5] = lsum;
    __syncthreads();
    if (tid == 0) {
        float s = 0.f;
#pragma unroll
        for (int i = 0; i < 8; i++) s += red[i];
        s_mean = s * (1.0f / HD);
    }
    __syncthreads();
    const float m = s_mean;

    float lv = 0.f;
    for (int i = tid; i < HD; i += 256) { float d = buf[i] - m; lv += d * d; }
    lv = warpSum(lv);
    __syncthreads();
    if ((tid & 31) == 0) red[tid >> 5] = lv;
    __syncthreads();
    if (tid == 0) {
        float s = 0.f;
#pragma unroll
        for (int i = 0; i < 8; i++) s += red[i];
        s_rstd = rsqrtf(s * (1.0f / HD) + 1e-12f);
    }
    __syncthreads();
    const float rs = s_rstd;
    for (int i = tid; i < HD; i += 256)
        out[(long long)row * HD + i] = (buf[i] - m) * rs * g[i] + b[i];
}

// ---------------- launch ------------------------------------------------------
extern "C" void kernel_launch(void* const* d_in, const int* in_sizes, int n_in,
                              void* d_out, int out_size)
{
    const float* cs   = (const float*)d_in[0];   // content_stream (Q,H)
    const float* mask = (const float*)d_in[1];   // content_mask (Q,C)
    const float* ctx  = (const float*)d_in[2];   // context (C,H)
    const float* pos  = (const float*)d_in[3];   // position_encoding (R,H)
    const float* cb   = (const float*)d_in[4];   // content_bias (N,D)
    const float* pb   = (const float*)d_in[5];   // position_bias (N,D)
    const float* seg  = (const float*)d_in[6];   // segment_encoding (2,N,D)
    const unsigned char* segm = (const unsigned char*)d_in[7]; // segment_matrix bool
    const float* sb   = (const float*)d_in[8];   // segment_bias (N,D)
    const float* Wq   = (const float*)d_in[9];
    const float* Wk   = (const float*)d_in[10];
    const float* Wv   = (const float*)d_in[11];
    const float* Wr   = (const float*)d_in[12];
    const float* Wo   = (const float*)d_in[13];
    const float* g1   = (const float*)d_in[14];
    const float* be1  = (const float*)d_in[15];
    const float* W1   = (const float*)d_in[16];
    const float* bf1  = (const float*)d_in[17];
    const float* W2   = (const float*)d_in[18];
    const float* bf2  = (const float*)d_in[19];
    const float* g2   = (const float*)d_in[20];
    const float* be2  = (const float*)d_in[21];
    float* out = (float*)d_out;

    float *pq, *pk, *pv, *pr, *psc, *pattn, *pao, *pfi, *pfh, *pfo;
    cudaGetSymbolAddress((void**)&pq,    g_q);
    cudaGetSymbolAddress((void**)&pk,    g_k);
    cudaGetSymbolAddress((void**)&pv,    g_v);
    cudaGetSymbolAddress((void**)&pr,    g_r);
    cudaGetSymbolAddress((void**)&psc,   g_scores);
    cudaGetSymbolAddress((void**)&pattn, g_attn);
    cudaGetSymbolAddress((void**)&pao,   g_attnout);
    cudaGetSymbolAddress((void**)&pfi,   g_ffnin);
    cudaGetSymbolAddress((void**)&pfh,   g_ffnh);
    cudaGetSymbolAddress((void**)&pfo,   g_ffnout);

    dim3 blk(256);

    // projections: X @ W  (W is [H, N*D] row-major)
    sgemm_kernel<false><<<dim3(HD / 64, QL / 64, 1), blk>>>(cs,  Wq, pq, QL, HD, HD, HD, HD, HD, 0, 0, 0, nullptr, 0);
    sgemm_kernel<false><<<dim3(HD / 64, CL / 64, 1), blk>>>(ctx, Wk, pk, CL, HD, HD, HD, HD, HD, 0, 0, 0, nullptr, 0);
    sgemm_kernel<false><<<dim3(HD / 64, CL / 64, 1), blk>>>(ctx, Wv, pv, CL, HD, HD, HD, HD, HD, 0, 0, 0, nullptr, 0);
    sgemm_kernel<false><<<dim3(HD / 64, RL / 64, 1), blk>>>(pos, Wr, pr, RL, HD, HD, HD, HD, HD, 0, 0, 0, nullptr, 0);

    // segment-bias dot products
    eseg_kernel<<<(2 * NH * QL) / 256, blk>>>(sb, seg);

    // fused relative-attention scores
    score_kernel<<<dim3(CL / 16, QL / 16, NH), blk>>>(mask, segm, cb, pb);

    // softmax rows
    softmax_kernel<<<NH * QL, blk>>>();

    // attn = probs @ v (per head, batched over z)
    sgemm_kernel<false><<<dim3(1, QL / 64, NH), blk>>>(
        psc, pv, pattn, QL, 64, CL, CL, HD, HD,
        (long long)QL * CL, 64, 64, nullptr, 0);

    // attn_out = attn @ Wo^T  (Wo is [H, N*D]; contract over N*D)
    sgemm_kernel<true><<<dim3(HD / 64, QL / 64, 1), blk>>>(
        pattn, Wo, pao, QL, HD, HD, HD, HD, HD, 0, 0, 0, nullptr, 0);

    // LN1(attn_out + content_stream) -> ffn_in
    ln_kernel<<<QL, blk>>>(pao, cs, g1, be1, pfi);

    // FFN
    sgemm_kernel<false><<<dim3(FF / 64, QL / 64, 1), blk>>>(
        pfi, W1, pfh, QL, FF, HD, HD, FF, FF, 0, 0, 0, bf1, 1);
    sgemm_kernel<false><<<dim3(HD / 64, QL / 64, 1), blk>>>(
        pfh, W2, pfo, QL, HD, FF, FF, HD, HD, 0, 0, 0, bf2, 0);

    // LN2(ffn_out + ffn_in) -> output
    ln_kernel<<<QL, blk>>>(pfo, pfi, g2, be2, out);
}

// round 4
// speedup vs baseline: 2.3345x; 2.3307x over previous
#include <cuda_runtime.h>
#include <cuda_bf16.h>
#include <math.h>
#include <stdint.h>

#define QL 2048
#define CL 2048
#define HD 1024
#define NH 16
#define DH 64
#define FF 4096
#define RL 4096

// ---------------- scratch ----------------
__device__ float g_q[QL * HD];
__device__ float g_k[CL * HD];
__device__ float g_v[CL * HD];
__device__ float g_r[RL * HD];
__device__ float g_scores[(size_t)NH * QL * CL];
__device__ float g_eseg[2 * NH * QL];
__device__ float g_attn[QL * HD];
__device__ float g_attnout[QL * HD];
__device__ float g_ffnin[QL * HD];
__device__ float g_ffnh[QL * FF];
__device__ float g_ffnout[QL * HD];
__device__ __nv_bfloat16 g_wqh[HD * HD], g_wql[HD * HD];
__device__ __nv_bfloat16 g_wkh[HD * HD], g_wkl[HD * HD];
__device__ __nv_bfloat16 g_wvh[HD * HD], g_wvl[HD * HD];
__device__ __nv_bfloat16 g_wrh[HD * HD], g_wrl[HD * HD];
__device__ __nv_bfloat16 g_woh[HD * HD], g_wol[HD * HD];
__device__ __nv_bfloat16 g_w1h[(size_t)FF * HD], g_w1l[(size_t)FF * HD];
__device__ __nv_bfloat16 g_w2h[(size_t)FF * HD], g_w2l[(size_t)FF * HD];
__device__ __nv_bfloat16 g_vth[HD * CL], g_vtl[HD * CL];

#define SWZ(o) ((o) ^ (((o) >> 3) & 0x70))

__device__ __forceinline__ void splitbf(float x, __nv_bfloat16& h, __nv_bfloat16& l) {
    h = __float2bfloat16(x);
    l = __float2bfloat16(x - __bfloat162float(h));
}
__device__ __forceinline__ void store4_split(char* th, char* tl, int row, int c4, float4 v) {
    uint32_t sw = SWZ((uint32_t)row * 128 + (uint32_t)c4 * 2);
    __nv_bfloat16 h0, l0, h1, l1, h2, l2, h3, l3;
    splitbf(v.x, h0, l0); splitbf(v.y, h1, l1); splitbf(v.z, h2, l2); splitbf(v.w, h3, l3);
    *(__nv_bfloat162*)(th + sw) = __halves2bfloat162(h0, h1);
    *(__nv_bfloat162*)(th + sw + 4) = __halves2bfloat162(h2, h3);
    *(__nv_bfloat162*)(tl + sw) = __halves2bfloat162(l0, l1);
    *(__nv_bfloat162*)(tl + sw + 4) = __halves2bfloat162(l2, l3);
}
__device__ __forceinline__ float warpSum(float v) {
#pragma unroll
    for (int o = 16; o; o >>= 1) v += __shfl_xor_sync(0xffffffffu, v, o);
    return v;
}
__device__ __forceinline__ float warpMax(float v) {
#pragma unroll
    for (int o = 16; o; o >>= 1) v = fmaxf(v, __shfl_xor_sync(0xffffffffu, v, o));
    return v;
}

// HMMA m16n8k16 bf16 -> fp32
__device__ __forceinline__ void mma_bf16(float* d, const uint32_t* a, const uint32_t* b) {
    asm volatile(
        "mma.sync.aligned.m16n8k16.row.col.f32.bf16.bf16.f32 "
        "{%0,%1,%2,%3}, {%4,%5,%6,%7}, {%8,%9}, {%0,%1,%2,%3};"
        : "+f"(d[0]), "+f"(d[1]), "+f"(d[2]), "+f"(d[3])
        : "r"(a[0]), "r"(a[1]), "r"(a[2]), "r"(a[3]), "r"(b[0]), "r"(b[1]));
}
// A fragment: a0=A[g][k0+2t..], a1=A[g+8][..], a2=A[g][k0+8+2t..], a3=A[g+8][k0+8+..]
__device__ __forceinline__ void ldA(uint32_t* a, const char* base, int row0, int k0, int g, int tig) {
    uint32_t c0 = (uint32_t)(k0 + 2 * tig) * 2;
    a[0] = *(const uint32_t*)(base + SWZ((uint32_t)(row0 + g) * 128 + c0));
    a[1] = *(const uint32_t*)(base + SWZ((uint32_t)(row0 + g + 8) * 128 + c0));
    a[2] = *(const uint32_t*)(base + SWZ((uint32_t)(row0 + g) * 128 + c0 + 16));
    a[3] = *(const uint32_t*)(base + SWZ((uint32_t)(row0 + g + 8) * 128 + c0 + 16));
}
// B fragment from [n][k] smem: b0=B[k0+2t..][n0+g], b1=B[k0+8+2t..][n0+g]
__device__ __forceinline__ void ldB(uint32_t* b, const char* base, int n0, int k0, int g, int tig) {
    uint32_t c0 = (uint32_t)(k0 + 2 * tig) * 2;
    b[0] = *(const uint32_t*)(base + SWZ((uint32_t)(n0 + g) * 128 + c0));
    b[1] = *(const uint32_t*)(base + SWZ((uint32_t)(n0 + g) * 128 + c0 + 16));
}

// ---------------- converters ----------------
__global__ void __launch_bounds__(256) convT_kernel(
    const float* __restrict__ in, __nv_bfloat16* __restrict__ oh,
    __nv_bfloat16* __restrict__ ol, int R, int Cc)
{
    __shared__ float t[32][33];
    const int tx = threadIdx.x & 31, ty8 = threadIdx.x >> 5;
    const int r0 = blockIdx.y * 32, c0 = blockIdx.x * 32;
    for (int j = ty8; j < 32; j += 8) t[j][tx] = in[(long long)(r0 + j) * Cc + c0 + tx];
    __syncthreads();
    for (int j = ty8; j < 32; j += 8) {
        __nv_bfloat16 h, l; splitbf(t[tx][j], h, l);
        long long o = (long long)(c0 + j) * R + r0 + tx;
        oh[o] = h; ol[o] = l;
    }
}
__global__ void __launch_bounds__(256) conv_kernel(
    const float* __restrict__ in, __nv_bfloat16* __restrict__ oh,
    __nv_bfloat16* __restrict__ ol, int n)
{
    int i = blockIdx.x * 256 + threadIdx.x;
    if (i < n) { __nv_bfloat16 h, l; splitbf(in[i], h, l); oh[i] = h; ol[i] = l; }
}

// ---------------- HMMA GEMM: C[M,N] = A[M,K](fp32) @ B[N,K](bf16 hi/lo)^T ----
// BM=128, BN=64, BK=64, 256 threads (8 warps, warp tile 32x32)
#define GM_AH 0
#define GM_AL 16384
#define GM_BH 32768
#define GM_BL 40960
#define GM_SMEM 49152

__global__ void __launch_bounds__(256) hmma_gemm_kernel(
    const float* __restrict__ A, const __nv_bfloat16* __restrict__ Bh,
    const __nv_bfloat16* __restrict__ Bl, float* __restrict__ C,
    int K, int lda, int ldb, int ldc,
    long long sA, long long sB, long long sC,
    const float* __restrict__ bias, int relu)
{
    extern __shared__ char smem[];
    const int tid = threadIdx.x, lane = tid & 31, w = tid >> 5;
    const int g = lane >> 2, tig = lane & 3;
    A += (long long)blockIdx.z * sA;
    Bh += (long long)blockIdx.z * sB;
    Bl += (long long)blockIdx.z * sB;
    C += (long long)blockIdx.z * sC;
    const int m0 = blockIdx.y * 128, n0 = blockIdx.x * 64;
    const int wm = (w >> 1) * 32, wn = (w & 1) * 32;

    float acc[2][4][4] = {};
    const int NC = K >> 6;
    for (int c = 0; c < NC; c++) {
        const int k0 = c << 6;
#pragma unroll
        for (int i = 0; i < 8; i++) {
            int gi = tid + (i << 8);
            int row = gi >> 4, c4 = (gi & 15) << 2;
            float4 v = *(const float4*)(A + (long long)(m0 + row) * lda + k0 + c4);
            store4_split(smem + GM_AH, smem + GM_AL, row, c4, v);
        }
#pragma unroll
        for (int i = 0; i < 2; i++) {
            int gi = tid + (i << 8);
            int row = gi >> 3, c16 = gi & 7;
            uint32_t sw = SWZ((uint32_t)row * 128 + (uint32_t)(c16 << 4));
            *(uint4*)(smem + GM_BH + sw) = *(const uint4*)(Bh + (long long)(n0 + row) * ldb + k0 + (c16 << 3));
            *(uint4*)(smem + GM_BL + sw) = *(const uint4*)(Bl + (long long)(n0 + row) * ldb + k0 + (c16 << 3));
        }
        __syncthreads();
#pragma unroll
        for (int ks = 0; ks < 4; ks++) {
            uint32_t ah[2][4], al[2][4], bh[4][2], bl[4][2];
#pragma unroll
            for (int mt = 0; mt < 2; mt++) {
                ldA(ah[mt], smem + GM_AH, wm + mt * 16, ks * 16, g, tig);
                ldA(al[mt], smem + GM_AL, wm + mt * 16, ks * 16, g, tig);
            }
#pragma unroll
            for (int nt = 0; nt < 4; nt++) {
                ldB(bh[nt], smem + GM_BH, wn + nt * 8, ks * 16, g, tig);
                ldB(bl[nt], smem + GM_BL, wn + nt * 8, ks * 16, g, tig);
            }
#pragma unroll
            for (int mt = 0; mt < 2; mt++)
#pragma unroll
                for (int nt = 0; nt < 4; nt++) {
                    mma_bf16(acc[mt][nt], ah[mt], bh[nt]);
                    mma_bf16(acc[mt][nt], ah[mt], bl[nt]);
                    mma_bf16(acc[mt][nt], al[mt], bh[nt]);
                }
        }
        __syncthreads();
    }
#pragma unroll
    for (int mt = 0; mt < 2; mt++)
#pragma unroll
        for (int nt = 0; nt < 4; nt++) {
            int row = m0 + wm + mt * 16 + g;
            int col = n0 + wn + nt * 8 + 2 * tig;
            float b0 = 0.f, b1 = 0.f;
            if (bias) { b0 = bias[col]; b1 = bias[col + 1]; }
            float2 v0 = { acc[mt][nt][0] + b0, acc[mt][nt][1] + b1 };
            float2 v1 = { acc[mt][nt][2] + b0, acc[mt][nt][3] + b1 };
            if (relu) {
                v0.x = fmaxf(v0.x, 0.f); v0.y = fmaxf(v0.y, 0.f);
                v1.x = fmaxf(v1.x, 0.f); v1.y = fmaxf(v1.y, 0.f);
            }
            *(float2*)(C + (long long)row * ldc + col) = v0;
            *(float2*)(C + (long long)(row + 8) * ldc + col) = v1;
        }
}

// ---------------- HMMA score kernel ----------------
// block: (head, 128 q, 128 c). 8 warps x 16 q rows.
#define S_QCH 0
#define S_QCL 16384
#define S_QPH 32768
#define S_QPL 49152
#define S_KH  65536
#define S_KL  81920
#define S_RH  98304
#define S_RL  131072
#define S_ST  163840
#define S_SMEM (163840 + 8 * 3200)

__global__ void __launch_bounds__(256) score_hmma_kernel(
    const float* __restrict__ mask, const unsigned char* __restrict__ segmat,
    const float* __restrict__ cb, const float* __restrict__ pb)
{
    extern __shared__ char smem[];
    const int tid = threadIdx.x, lane = tid & 31, w = tid >> 5;
    const int g = lane >> 2, tig = lane & 3;
    const int n = blockIdx.z, q0 = blockIdx.y * 128, c0 = blockIdx.x * 128;

    // load qc/qp/k tiles (128 x 64), split
#pragma unroll
    for (int i = 0; i < 8; i++) {
        int gi = tid + (i << 8);
        int row = gi >> 4, c4 = (gi & 15) << 2;
        float4 qv = *(const float4*)(g_q + (long long)(q0 + row) * HD + n * DH + c4);
        float4 cbv = *(const float4*)(cb + n * DH + c4);
        float4 pbv = *(const float4*)(pb + n * DH + c4);
        float4 a = { qv.x + cbv.x, qv.y + cbv.y, qv.z + cbv.z, qv.w + cbv.w };
        float4 b = { qv.x + pbv.x, qv.y + pbv.y, qv.z + pbv.z, qv.w + pbv.w };
        store4_split(smem + S_QCH, smem + S_QCL, row, c4, a);
        store4_split(smem + S_QPH, smem + S_QPL, row, c4, b);
        float4 kv = *(const float4*)(g_k + (long long)(c0 + row) * HD + n * DH + c4);
        store4_split(smem + S_KH, smem + S_KL, row, c4, kv);
    }
    // r band: 256 rows starting at rstart (clamped)
    const int rstart = QL + c0 - q0 - 127;
#pragma unroll
    for (int i = 0; i < 16; i++) {
        int gi = tid + (i << 8);
        int row = gi >> 4, c4 = (gi & 15) << 2;
        int rg = rstart + row; if (rg > RL - 1) rg = RL - 1;
        float4 rv = *(const float4*)(g_r + (long long)rg * HD + n * DH + c4);
        store4_split(smem + S_RH, smem + S_RL, row, c4, rv);
    }
    __syncthreads();

    const int w0 = w * 16;
    const float e0a = g_eseg[(0 * NH + n) * QL + q0 + w0 + g];
    const float e1a = g_eseg[(1 * NH + n) * QL + q0 + w0 + g];
    const float e0b = g_eseg[(0 * NH + n) * QL + q0 + w0 + g + 8];
    const float e1b = g_eseg[(1 * NH + n) * QL + q0 + w0 + g + 8];
    float* stg = (float*)(smem + S_ST + w * 3200);   // [16][50]

    for (int ch = 0; ch < 4; ch++) {
        float accA[4][4] = {};
        float accB[6][4] = {};
        const int s0 = ch * 32 - w0 + 112;
#pragma unroll
        for (int ks = 0; ks < 4; ks++) {
            uint32_t ach[4], acl[4], aph[4], apl[4];
            ldA(ach, smem + S_QCH, w0, ks * 16, g, tig);
            ldA(acl, smem + S_QCL, w0, ks * 16, g, tig);
            ldA(aph, smem + S_QPH, w0, ks * 16, g, tig);
            ldA(apl, smem + S_QPL, w0, ks * 16, g, tig);
#pragma unroll
            for (int nt = 0; nt < 4; nt++) {
                uint32_t bh[2], bl[2];
                ldB(bh, smem + S_KH, ch * 32 + nt * 8, ks * 16, g, tig);
                ldB(bl, smem + S_KL, ch * 32 + nt * 8, ks * 16, g, tig);
                mma_bf16(accA[nt], ach, bh);
                mma_bf16(accA[nt], ach, bl);
                mma_bf16(accA[nt], acl, bh);
            }
#pragma unroll
            for (int nt = 0; nt < 6; nt++) {
                uint32_t bh[2], bl[2];
                ldB(bh, smem + S_RH, s0 + nt * 8, ks * 16, g, tig);
                ldB(bl, smem + S_RL, s0 + nt * 8, ks * 16, g, tig);
                mma_bf16(accB[nt], aph, bh);
                mma_bf16(accB[nt], aph, bl);
                mma_bf16(accB[nt], apl, bh);
            }
        }
        // stage bd (warp-private)
#pragma unroll
        for (int nt = 0; nt < 6; nt++) {
            int cc = nt * 8 + 2 * tig;
            stg[g * 50 + cc] = accB[nt][0];
            stg[g * 50 + cc + 1] = accB[nt][1];
            stg[(g + 8) * 50 + cc] = accB[nt][2];
            stg[(g + 8) * 50 + cc + 1] = accB[nt][3];
        }
        __syncwarp();
        // epilogue
#pragma unroll
        for (int nt = 0; nt < 4; nt++) {
            const int jl = nt * 8 + 2 * tig;           // 0..31 local col
            const int rla = jl - g + 15;
            const int rlb = jl - g + 7;
            const float bd0 = stg[g * 50 + rla], bd1 = stg[g * 50 + rla + 1];
            const float bd2 = stg[(g + 8) * 50 + rlb], bd3 = stg[(g + 8) * 50 + rlb + 1];
            const int qa = q0 + w0 + g, cc = c0 + ch * 32 + jl;
            const size_t ma = (size_t)qa * CL + cc;
            const size_t mb = (size_t)(qa + 8) * CL + cc;
            float2 mka = *(const float2*)(mask + ma);
            float2 mkb = *(const float2*)(mask + mb);
            uchar2 sga = *(const uchar2*)(segmat + ma);
            uchar2 sgb = *(const uchar2*)(segmat + mb);
            float2 oa, ob;
            oa.x = (accA[nt][0] + bd0 + (sga.x ? e1a : e0a)) * 0.125f - 1e30f * mka.x;
            oa.y = (accA[nt][1] + bd1 + (sga.y ? e1a : e0a)) * 0.125f - 1e30f * mka.y;
            ob.x = (accA[nt][2] + bd2 + (sgb.x ? e1b : e0b)) * 0.125f - 1e30f * mkb.x;
            ob.y = (accA[nt][3] + bd3 + (sgb.y ? e1b : e0b)) * 0.125f - 1e30f * mkb.y;
            *(float2*)(g_scores + ((size_t)n * QL + qa) * CL + cc) = oa;
            *(float2*)(g_scores + ((size_t)n * QL + qa + 8) * CL + cc) = ob;
        }
        __syncwarp();
    }
}

// ---------------- eseg ----------------
__global__ void __launch_bounds__(256) eseg_kernel(
    const float* __restrict__ sb, const float* __restrict__ seg)
{
    int idx = blockIdx.x * 256 + threadIdx.x;
    if (idx >= 2 * NH * QL) return;
    int s = idx / (NH * QL), n = (idx / QL) % NH, qi = idx % QL;
    const float* qr = g_q + (long long)qi * HD + n * DH;
    const float* sbr = sb + n * DH;
    const float* sg = seg + s * (NH * DH) + n * DH;
    float acc = 0.f;
#pragma unroll
    for (int d = 0; d < DH; d++) acc += (qr[d] + sbr[d]) * sg[d];
    g_eseg[idx] = acc;
}

// ---------------- softmax ----------------
__global__ void __launch_bounds__(256) softmax_kernel()
{
    const size_t row = blockIdx.x;
    float* p = g_scores + row * (size_t)CL;
    const int tid = threadIdx.x;
    __shared__ float red[8];
    __shared__ float sh;
    float v[8];
    float mx = -3.4e38f;
#pragma unroll
    for (int j = 0; j < 8; j++) { v[j] = p[tid + 256 * j]; mx = fmaxf(mx, v[j]); }
    mx = warpMax(mx);
    if ((tid & 31) == 0) red[tid >> 5] = mx;
    __syncthreads();
    if (tid == 0) {
        float m = red[0];
#pragma unroll
        for (int i = 1; i < 8; i++) m = fmaxf(m, red[i]);
        sh = m;
    }
    __syncthreads();
    mx = sh;
    float sum = 0.f;
#pragma unroll
    for (int j = 0; j < 8; j++) { v[j] = __expf(v[j] - mx); sum += v[j]; }
    sum = warpSum(sum);
    __syncthreads();
    if ((tid & 31) == 0) red[tid >> 5] = sum;
    __syncthreads();
    if (tid == 0) {
        float s = 0.f;
#pragma unroll
        for (int i = 0; i < 8; i++) s += red[i];
        sh = 1.0f / s;
    }
    __syncthreads();
    const float inv = sh;
#pragma unroll
    for (int j = 0; j < 8; j++) p[tid + 256 * j] = v[j] * inv;
}

// ---------------- residual + LN ----------------
__global__ void __launch_bounds__(256) ln_kernel(
    const float* __restrict__ x, const float* __restrict__ res,
    const float* __restrict__ g, const float* __restrict__ b,
    float* __restrict__ out)
{
    const int row = blockIdx.x;
    __shared__ float buf[HD];
    __shared__ float red[8];
    __shared__ float s_mean, s_rstd;
    const int tid = threadIdx.x;
    float lsum = 0.f;
    for (int i = tid; i < HD; i += 256) {
        float v = x[(long long)row * HD + i] + res[(long long)row * HD + i];
        buf[i] = v; lsum += v;
    }
    lsum = warpSum(lsum);
    if ((tid & 31) == 0) red[tid >> 5] = lsum;
    __syncthreads();
    if (tid == 0) {
        float s = 0.f;
#pragma unroll
        for (int i = 0; i < 8; i++) s += red[i];
        s_mean = s * (1.0f / HD);
    }
    __syncthreads();
    const float m = s_mean;
    float lv = 0.f;
    for (int i = tid; i < HD; i += 256) { float d = buf[i] - m; lv += d * d; }
    lv = warpSum(lv);
    __syncthreads();
    if ((tid & 31) == 0) red[tid >> 5] = lv;
    __syncthreads();
    if (tid == 0) {
        float s = 0.f;
#pragma unroll
        for (int i = 0; i < 8; i++) s += red[i];
        s_rstd = rsqrtf(s * (1.0f / HD) + 1e-12f);
    }
    __syncthreads();
    const float rs = s_rstd;
    for (int i = tid; i < HD; i += 256)
        out[(long long)row * HD + i] = (buf[i] - m) * rs * g[i] + b[i];
}

// ---------------- launch ----------------
extern "C" void kernel_launch(void* const* d_in, const int* in_sizes, int n_in,
                              void* d_out, int out_size)
{
    const float* cs = (const float*)d_in[0];
    const float* mask = (const float*)d_in[1];
    const float* ctx = (const float*)d_in[2];
    const float* pos = (const float*)d_in[3];
    const float* cb = (const float*)d_in[4];
    const float* pb = (const float*)d_in[5];
    const float* seg = (const float*)d_in[6];
    const unsigned char* segm = (const unsigned char*)d_in[7];
    const float* sbb = (const float*)d_in[8];
    const float* Wq = (const float*)d_in[9];
    const float* Wk = (const float*)d_in[10];
    const float* Wv = (const float*)d_in[11];
    const float* Wr = (const float*)d_in[12];
    const float* Wo = (const float*)d_in[13];
    const float* g1 = (const float*)d_in[14];
    const float* be1 = (const float*)d_in[15];
    const float* W1 = (const float*)d_in[16];
    const float* bf1 = (const float*)d_in[17];
    const float* W2 = (const float*)d_in[18];
    const float* bf2 = (const float*)d_in[19];
    const float* g2 = (const float*)d_in[20];
    const float* be2 = (const float*)d_in[21];
    float* out = (float*)d_out;

    float *pq, *pk, *pv, *pr, *psc, *pattn, *pao, *pfi, *pfh, *pfo;
    __nv_bfloat16 *wqh, *wql, *wkh, *wkl, *wvh, *wvl, *wrh, *wrl, *woh, *wol;
    __nv_bfloat16 *w1h, *w1l, *w2h, *w2l, *vth, *vtl;
    cudaGetSymbolAddress((void**)&pq, g_q);
    cudaGetSymbolAddress((void**)&pk, g_k);
    cudaGetSymbolAddress((void**)&pv, g_v);
    cudaGetSymbolAddress((void**)&pr, g_r);
    cudaGetSymbolAddress((void**)&psc, g_scores);
    cudaGetSymbolAddress((void**)&pattn, g_attn);
    cudaGetSymbolAddress((void**)&pao, g_attnout);
    cudaGetSymbolAddress((void**)&pfi, g_ffnin);
    cudaGetSymbolAddress((void**)&pfh, g_ffnh);
    cudaGetSymbolAddress((void**)&pfo, g_ffnout);
    cudaGetSymbolAddress((void**)&wqh, g_wqh); cudaGetSymbolAddress((void**)&wql, g_wql);
    cudaGetSymbolAddress((void**)&wkh, g_wkh); cudaGetSymbolAddress((void**)&wkl, g_wkl);
    cudaGetSymbolAddress((void**)&wvh, g_wvh); cudaGetSymbolAddress((void**)&wvl, g_wvl);
    cudaGetSymbolAddress((void**)&wrh, g_wrh); cudaGetSymbolAddress((void**)&wrl, g_wrl);
    cudaGetSymbolAddress((void**)&woh, g_woh); cudaGetSymbolAddress((void**)&wol, g_wol);
    cudaGetSymbolAddress((void**)&w1h, g_w1h); cudaGetSymbolAddress((void**)&w1l, g_w1l);
    cudaGetSymbolAddress((void**)&w2h, g_w2h); cudaGetSymbolAddress((void**)&w2l, g_w2l);
    cudaGetSymbolAddress((void**)&vth, g_vth); cudaGetSymbolAddress((void**)&vtl, g_vtl);

    cudaFuncSetAttribute(hmma_gemm_kernel, cudaFuncAttributeMaxDynamicSharedMemorySize, GM_SMEM);
    cudaFuncSetAttribute(score_hmma_kernel, cudaFuncAttributeMaxDynamicSharedMemorySize, S_SMEM);

    dim3 blk(256);
    convT_kernel<<<dim3(HD / 32, HD / 32), blk>>>(Wq, wqh, wql, HD, HD);
    convT_kernel<<<dim3(HD / 32, HD / 32), blk>>>(Wk, wkh, wkl, HD, HD);
    convT_kernel<<<dim3(HD / 32, HD / 32), blk>>>(Wv, wvh, wvl, HD, HD);
    convT_kernel<<<dim3(HD / 32, HD / 32), blk>>>(Wr, wrh, wrl, HD, HD);
    conv_kernel<<<(HD * HD) / 256, blk>>>(Wo, woh, wol, HD * HD);
    convT_kernel<<<dim3(FF / 32, HD / 32), blk>>>(W1, w1h, w1l, HD, FF);
    convT_kernel<<<dim3(HD / 32, FF / 32), blk>>>(W2, w2h, w2l, FF, HD);

    hmma_gemm_kernel<<<dim3(HD / 64, QL / 128, 1), blk, GM_SMEM>>>(cs, wqh, wql, pq, HD, HD, HD, HD, 0, 0, 0, nullptr, 0);
    hmma_gemm_kernel<<<dim3(HD / 64, CL / 128, 1), blk, GM_SMEM>>>(ctx, wkh, wkl, pk, HD, HD, HD, HD, 0, 0, 0, nullptr, 0);
    hmma_gemm_kernel<<<dim3(HD / 64, CL / 128, 1), blk, GM_SMEM>>>(ctx, wvh, wvl, pv, HD, HD, HD, HD, 0, 0, 0, nullptr, 0);
    hmma_gemm_kernel<<<dim3(HD / 64, RL / 128, 1), blk, GM_SMEM>>>(pos, wrh, wrl, pr, HD, HD, HD, HD, 0, 0, 0, nullptr, 0);

    convT_kernel<<<dim3(HD / 32, CL / 32), blk>>>(pv, vth, vtl, CL, HD);
    eseg_kernel<<<(2 * NH * QL) / 256, blk>>>(sbb, seg);

    score_hmma_kernel<<<dim3(CL / 128, QL / 128, NH), blk, S_SMEM>>>(mask, segm, cb, pb);
    softmax_kernel<<<NH * QL, blk>>>();

    // attn = probs @ v (per head)
    hmma_gemm_kernel<<<dim3(1, QL / 128, NH), blk, GM_SMEM>>>(
        psc, vth, vtl, pattn, CL, CL, CL, HD,
        (long long)QL * CL, (long long)64 * CL, 64, nullptr, 0);

    hmma_gemm_kernel<<<dim3(HD / 64, QL / 128, 1), blk, GM_SMEM>>>(pattn, woh, wol, pao, HD, HD, HD, HD, 0, 0, 0, nullptr, 0);
    ln_kernel<<<QL, blk>>>(pao, cs, g1, be1, pfi);

    hmma_gemm_kernel<<<dim3(FF / 64, QL / 128, 1), blk, GM_SMEM>>>(pfi, w1h, w1l, pfh, HD, HD, HD, FF, 0, 0, 0, bf1, 1);
    hmma_gemm_kernel<<<dim3(HD / 64, QL / 128, 1), blk, GM_SMEM>>>(pfh, w2h, w2l, pfo, FF, FF, FF, HD, 0, 0, 0, bf2, 0);

    ln_kernel<<<QL, blk>>>(pfo, pfi, g2, be2, out);
}

// round 5
// speedup vs baseline: 3.2891x; 1.4089x over previous
#include <cuda_runtime.h>
#include <cuda_bf16.h>
#include <math.h>
#include <stdint.h>

#define QL 2048
#define CL 2048
#define HD 1024
#define NH 16
#define DH 64
#define FF 4096
#define RL 4096
typedef __nv_bfloat16 bf16;
typedef __nv_bfloat162 bf162;

// ---------------- scratch ----------------
__device__ float g_v[CL * HD];
__device__ float g_scores[(size_t)NH * QL * CL];
__device__ float g_eseg[2 * NH * QL];
__device__ float g_attnout[QL * HD];
__device__ float g_ffnin[QL * HD];
__device__ float g_ffnout[QL * HD];
// split bf16 buffers
__device__ bf16 g_csh[QL * HD], g_csl[QL * HD];
__device__ bf16 g_ctxh[CL * HD], g_ctxl[CL * HD];
__device__ bf16 g_posh[RL * HD], g_posl[RL * HD];
__device__ bf16 g_qch[QL * HD], g_qcl[QL * HD];
__device__ bf16 g_qph[QL * HD], g_qpl[QL * HD];
__device__ bf16 g_kh[CL * HD], g_kl[CL * HD];
__device__ bf16 g_rh[RL * HD], g_rl[RL * HD];
__device__ bf16 g_ph[(size_t)NH * QL * CL], g_pl[(size_t)NH * QL * CL];
__device__ bf16 g_ath[QL * HD], g_atl[QL * HD];
__device__ bf16 g_fih[QL * HD], g_fil[QL * HD];
__device__ bf16 g_fhh[(size_t)QL * FF], g_fhl[(size_t)QL * FF];
// split weights
__device__ bf16 g_wqh[HD * HD], g_wql[HD * HD];
__device__ bf16 g_wkh[HD * HD], g_wkl[HD * HD];
__device__ bf16 g_wvh[HD * HD], g_wvl[HD * HD];
__device__ bf16 g_wrh[HD * HD], g_wrl[HD * HD];
__device__ bf16 g_woh[HD * HD], g_wol[HD * HD];
__device__ bf16 g_w1h[(size_t)FF * HD], g_w1l[(size_t)FF * HD];
__device__ bf16 g_w2h[(size_t)FF * HD], g_w2l[(size_t)FF * HD];
__device__ bf16 g_vth[HD * CL], g_vtl[HD * CL];

#define SWZ(o) ((o) ^ (((o) >> 3) & 0x70))

__device__ __forceinline__ uint32_t smem_u32(const void* p) {
    uint32_t a;
    asm("{ .reg .u64 t; cvta.to.shared.u64 t, %1; cvt.u32.u64 %0, t; }" : "=r"(a) : "l"(p));
    return a;
}
__device__ __forceinline__ void cpasync16(uint32_t s, const void* g) {
    asm volatile("cp.async.cg.shared.global [%0], [%1], 16;" :: "r"(s), "l"(g));
}
#define CP_COMMIT() asm volatile("cp.async.commit_group;")
#define CP_WAIT(n) asm volatile("cp.async.wait_group %0;" :: "n"(n))

__device__ __forceinline__ void splitbf(float x, bf16& h, bf16& l) {
    h = __float2bfloat16(x);
    l = __float2bfloat16(x - __bfloat162float(h));
}
__device__ __forceinline__ void wsplit2(bf16* oh, bf16* ol, long long off, float x, float y) {
    bf16 h0, l0, h1, l1;
    splitbf(x, h0, l0); splitbf(y, h1, l1);
    *(bf162*)(oh + off) = __halves2bfloat162(h0, h1);
    *(bf162*)(ol + off) = __halves2bfloat162(l0, l1);
}
__device__ __forceinline__ float warpSum(float v) {
#pragma unroll
    for (int o = 16; o; o >>= 1) v += __shfl_xor_sync(0xffffffffu, v, o);
    return v;
}
__device__ __forceinline__ float warpMax(float v) {
#pragma unroll
    for (int o = 16; o; o >>= 1) v = fmaxf(v, __shfl_xor_sync(0xffffffffu, v, o));
    return v;
}
__device__ __forceinline__ void mma_bf16(float* d, const uint32_t* a, const uint32_t* b) {
    asm volatile(
        "mma.sync.aligned.m16n8k16.row.col.f32.bf16.bf16.f32 "
        "{%0,%1,%2,%3}, {%4,%5,%6,%7}, {%8,%9}, {%0,%1,%2,%3};"
        : "+f"(d[0]), "+f"(d[1]), "+f"(d[2]), "+f"(d[3])
        : "r"(a[0]), "r"(a[1]), "r"(a[2]), "r"(a[3]), "r"(b[0]), "r"(b[1]));
}
// ldmatrix x4 over a [rows][64cols bf16] swizzled tile (128B rows).
// Loads 16 rows x 16 cols: r0 = (rows0-7,k0-7) r1=(rows8-15,k0-7) r2=(rows0-7,k8-15) r3=(rows8-15,k8-15)
__device__ __forceinline__ void ldm4(uint32_t* r, uint32_t base, int row0, int k0, int lane) {
    int row = row0 + (lane & 15);
    int kc = k0 + ((lane >> 4) << 3);
    uint32_t addr = base + SWZ((uint32_t)row * 128 + (uint32_t)kc * 2);
    asm volatile("ldmatrix.sync.aligned.m8n8.x4.shared.b16 {%0,%1,%2,%3}, [%4];"
                 : "=r"(r[0]), "=r"(r[1]), "=r"(r[2]), "=r"(r[3]) : "r"(addr));
}

// ---------------- converters ----------------
__global__ void __launch_bounds__(256) convT_kernel(
    const float* __restrict__ in, bf16* __restrict__ oh, bf16* __restrict__ ol, int R, int Cc)
{
    __shared__ float t[32][33];
    const int tx = threadIdx.x & 31, ty8 = threadIdx.x >> 5;
    const int r0 = blockIdx.y * 32, c0 = blockIdx.x * 32;
    for (int j = ty8; j < 32; j += 8) t[j][tx] = in[(long long)(r0 + j) * Cc + c0 + tx];
    __syncthreads();
    for (int j = ty8; j < 32; j += 8) {
        bf16 h, l; splitbf(t[tx][j], h, l);
        long long o = (long long)(c0 + j) * R + r0 + tx;
        oh[o] = h; ol[o] = l;
    }
}
__global__ void __launch_bounds__(256) conv_kernel(
    const float* __restrict__ in, bf16* __restrict__ oh, bf16* __restrict__ ol, int n)
{
    int i = blockIdx.x * 256 + threadIdx.x;
    if (i < n) { bf16 h, l; splitbf(in[i], h, l); oh[i] = h; ol[i] = l; }
}
__global__ void __launch_bounds__(256) split4_kernel(
    const float* __restrict__ in, bf16* __restrict__ oh, bf16* __restrict__ ol, int n4)
{
    int i = blockIdx.x * 256 + threadIdx.x;
    if (i >= n4) return;
    float4 v = *(const float4*)(in + i * 4);
    wsplit2(oh, ol, (long long)i * 4, v.x, v.y);
    wsplit2(oh, ol, (long long)i * 4 + 2, v.z, v.w);
}

// ---------------- HMMA GEMM: C[M,N] = A[M,K] @ B[N,K]^T, all bf16 hi/lo ------
// BM=128, BN=64, BK=64, 256 threads (8 warps 4x2, warp tile 32x32), 2-stage cp.async
#define ST_AH 0
#define ST_AL 16384
#define ST_BH 32768
#define ST_BL 40960
#define ST_SZ 49152
#define GM_SMEM (2 * ST_SZ)

__global__ void __launch_bounds__(256) hmma_gemm_kernel(
    const bf16* __restrict__ Ah, const bf16* __restrict__ Al,
    const bf16* __restrict__ Bh, const bf16* __restrict__ Bl,
    float* __restrict__ C, const float* __restrict__ biasC,
    bf16* __restrict__ O1h, bf16* __restrict__ O1l, const float* __restrict__ bias1,
    bf16* __restrict__ O2h, bf16* __restrict__ O2l, const float* __restrict__ bias2,
    int K, int lda, int ldb, int ldc,
    long long sA, long long sB, long long sC, int relu)
{
    extern __shared__ char smem[];
    const uint32_t sbase = smem_u32(smem);
    const int tid = threadIdx.x, lane = tid & 31, w = tid >> 5;
    const int g = lane >> 2, tig = lane & 3;
    Ah += (long long)blockIdx.z * sA; Al += (long long)blockIdx.z * sA;
    Bh += (long long)blockIdx.z * sB; Bl += (long long)blockIdx.z * sB;
    const long long co = (long long)blockIdx.z * sC;
    const int m0 = blockIdx.y * 128, n0 = blockIdx.x * 64;
    const int wm = (w >> 1) * 32, wn = (w & 1) * 32;

    // per-thread load units
    const int au = tid;            // A: 1024 units, 4 per thread
    const int bu = tid;            // B: 512 units, 2 per thread

    auto load_stage = [&](int s, int k0) {
        uint32_t sb = sbase + s * ST_SZ;
#pragma unroll
        for (int i = 0; i < 4; i++) {
            int u = au + (i << 8);
            int row = u >> 3, c16 = u & 7;
            uint32_t sw = SWZ((uint32_t)row * 128 + (uint32_t)(c16 << 4));
            const long long gofs = (long long)(m0 + row) * lda + k0 + (c16 << 3);
            cpasync16(sb + ST_AH + sw, Ah + gofs);
            cpasync16(sb + ST_AL + sw, Al + gofs);
        }
#pragma unroll
        for (int i = 0; i < 2; i++) {
            int u = bu + (i << 8);
            int row = u >> 3, c16 = u & 7;
            uint32_t sw = SWZ((uint32_t)row * 128 + (uint32_t)(c16 << 4));
            const long long gofs = (long long)(n0 + row) * ldb + k0 + (c16 << 3);
            cpasync16(sb + ST_BH + sw, Bh + gofs);
            cpasync16(sb + ST_BL + sw, Bl + gofs);
        }
    };

    float acc[2][4][4] = {};
    const int NC = K >> 6;
    load_stage(0, 0);
    CP_COMMIT();
    for (int c = 0; c < NC; c++) {
        if (c + 1 < NC) { load_stage((c + 1) & 1, (c + 1) << 6); CP_COMMIT(); CP_WAIT(1); }
        else CP_WAIT(0);
        __syncthreads();
        const uint32_t sb = sbase + (c & 1) * ST_SZ;
#pragma unroll
        for (int ks = 0; ks < 4; ks++) {
            uint32_t ah[2][4], al[2][4], bh[2][4], bl[2][4];
            ldm4(ah[0], sb + ST_AH, wm, ks * 16, lane);
            ldm4(ah[1], sb + ST_AH, wm + 16, ks * 16, lane);
            ldm4(al[0], sb + ST_AL, wm, ks * 16, lane);
            ldm4(al[1], sb + ST_AL, wm + 16, ks * 16, lane);
            ldm4(bh[0], sb + ST_BH, wn, ks * 16, lane);
            ldm4(bh[1], sb + ST_BH, wn + 16, ks * 16, lane);
            ldm4(bl[0], sb + ST_BL, wn, ks * 16, lane);
            ldm4(bl[1], sb + ST_BL, wn + 16, ks * 16, lane);
#pragma unroll
            for (int mt = 0; mt < 2; mt++)
#pragma unroll
                for (int nt = 0; nt < 4; nt++) {
                    const int p = nt >> 1, o = nt & 1;
                    uint32_t fbh[2] = { bh[p][o], bh[p][2 + o] };
                    uint32_t fbl[2] = { bl[p][o], bl[p][2 + o] };
                    mma_bf16(acc[mt][nt], ah[mt], fbh);
                    mma_bf16(acc[mt][nt], ah[mt], fbl);
                    mma_bf16(acc[mt][nt], al[mt], fbh);
                }
        }
        __syncthreads();
    }

#pragma unroll
    for (int mt = 0; mt < 2; mt++)
#pragma unroll
        for (int nt = 0; nt < 4; nt++) {
#pragma unroll
            for (int h = 0; h < 2; h++) {
                const int row = m0 + wm + mt * 16 + g + h * 8;
                const int col = n0 + wn + nt * 8 + 2 * tig;
                float x = acc[mt][nt][h * 2], y = acc[mt][nt][h * 2 + 1];
                const long long off = (long long)row * ldc + col + co;
                if (C) {
                    float b0 = biasC ? biasC[col] : 0.f, b1 = biasC ? biasC[col + 1] : 0.f;
                    float2 o = { x + b0, y + b1 };
                    *(float2*)(C + off) = o;
                }
                if (O1h) {
                    float b0 = bias1 ? bias1[col] : 0.f, b1 = bias1 ? bias1[col + 1] : 0.f;
                    float vx = x + b0, vy = y + b1;
                    if (relu) { vx = fmaxf(vx, 0.f); vy = fmaxf(vy, 0.f); }
                    wsplit2(O1h, O1l, off, vx, vy);
                }
                if (O2h) {
                    float b0 = bias2 ? bias2[col] : 0.f, b1 = bias2 ? bias2[col + 1] : 0.f;
                    wsplit2(O2h, O2l, off, x + b0, y + b1);
                }
            }
        }
}

// ---------------- HMMA score kernel ----------------
#define S_QCH 0
#define S_QCL 16384
#define S_QPH 32768
#define S_QPL 49152
#define S_KH  65536
#define S_KL  81920
#define S_RH  98304
#define S_RL  131072
#define S_ST  163840
#define S_SMEM (163840 + 8 * 3200)

__global__ void __launch_bounds__(256) score_hmma_kernel(
    const float* __restrict__ mask, const unsigned char* __restrict__ segmat)
{
    extern __shared__ char smem[];
    const uint32_t sbase = smem_u32(smem);
    const int tid = threadIdx.x, lane = tid & 31, w = tid >> 5;
    const int g = lane >> 2, tig = lane & 3;
    const int n = blockIdx.z, q0 = blockIdx.y * 128, c0 = blockIdx.x * 128;
    const int nDH = n * DH;

    // 128x64 bf16 tiles: 1024 16B units each (4/thread)
    auto ldtile = [&](int dsth, int dstl, const bf16* srch, const bf16* srcl, long long rbase, int ldg) {
#pragma unroll
        for (int i = 0; i < 4; i++) {
            int u = tid + (i << 8);
            int row = u >> 3, c16 = u & 7;
            uint32_t sw = SWZ((uint32_t)row * 128 + (uint32_t)(c16 << 4));
            long long gofs = (rbase + row) * ldg + nDH + (c16 << 3);
            *(uint4*)(smem + dsth + sw) = *(const uint4*)(srch + gofs);
            *(uint4*)(smem + dstl + sw) = *(const uint4*)(srcl + gofs);
        }
    };
    ldtile(S_QCH, S_QCL, g_qch, g_qcl, q0, HD);
    ldtile(S_QPH, S_QPL, g_qph, g_qpl, q0, HD);
    ldtile(S_KH, S_KL, g_kh, g_kl, c0, HD);
    const int rstart = QL + c0 - q0 - 127;
#pragma unroll
    for (int i = 0; i < 8; i++) {
        int u = tid + (i << 8);
        int row = u >> 3, c16 = u & 7;
        int rg = rstart + row; if (rg > RL - 1) rg = RL - 1;
        uint32_t sw = SWZ((uint32_t)row * 128 + (uint32_t)(c16 << 4));
        long long gofs = (long long)rg * HD + nDH + (c16 << 3);
        *(uint4*)(smem + S_RH + sw) = *(const uint4*)(g_rh + gofs);
        *(uint4*)(smem + S_RL + sw) = *(const uint4*)(g_rl + gofs);
    }
    __syncthreads();

    const int w0 = w * 16;
    const float e0a = g_eseg[(0 * NH + n) * QL + q0 + w0 + g];
    const float e1a = g_eseg[(1 * NH + n) * QL + q0 + w0 + g];
    const float e0b = g_eseg[(0 * NH + n) * QL + q0 + w0 + g + 8];
    const float e1b = g_eseg[(1 * NH + n) * QL + q0 + w0 + g + 8];
    float* stg = (float*)(smem + S_ST + w * 3200);   // [16][50]

    for (int ch = 0; ch < 4; ch++) {
        float accA[4][4] = {};
        float accB[6][4] = {};
        const int s0 = ch * 32 - w0 + 112;
#pragma unroll
        for (int ks = 0; ks < 4; ks++) {
            uint32_t ach[4], acl[4], aph[4], apl[4];
            ldm4(ach, sbase + S_QCH, w0, ks * 16, lane);
            ldm4(acl, sbase + S_QCL, w0, ks * 16, lane);
            ldm4(aph, sbase + S_QPH, w0, ks * 16, lane);
            ldm4(apl, sbase + S_QPL, w0, ks * 16, lane);
            uint32_t kh[2][4], kl[2][4];
            ldm4(kh[0], sbase + S_KH, ch * 32, ks * 16, lane);
            ldm4(kh[1], sbase + S_KH, ch * 32 + 16, ks * 16, lane);
            ldm4(kl[0], sbase + S_KL, ch * 32, ks * 16, lane);
            ldm4(kl[1], sbase + S_KL, ch * 32 + 16, ks * 16, lane);
#pragma unroll
            for (int nt = 0; nt < 4; nt++) {
                const int p = nt >> 1, o = nt & 1;
                uint32_t fbh[2] = { kh[p][o], kh[p][2 + o] };
                uint32_t fbl[2] = { kl[p][o], kl[p][2 + o] };
                mma_bf16(accA[nt], ach, fbh);
                mma_bf16(accA[nt], ach, fbl);
                mma_bf16(accA[nt], acl, fbh);
            }
            uint32_t rh[3][4], rl[3][4];
#pragma unroll
            for (int p = 0; p < 3; p++) {
                ldm4(rh[p], sbase + S_RH, s0 + p * 16, ks * 16, lane);
                ldm4(rl[p], sbase + S_RL, s0 + p * 16, ks * 16, lane);
            }
#pragma unroll
            for (int nt = 0; nt < 6; nt++) {
                const int p = nt >> 1, o = nt & 1;
                uint32_t fbh[2] = { rh[p][o], rh[p][2 + o] };
                uint32_t fbl[2] = { rl[p][o], rl[p][2 + o] };
                mma_bf16(accB[nt], aph, fbh);
                mma_bf16(accB[nt], aph, fbl);
                mma_bf16(accB[nt], apl, fbh);
            }
        }
#pragma unroll
        for (int nt = 0; nt < 6; nt++) {
            int cc = nt * 8 + 2 * tig;
            stg[g * 50 + cc] = accB[nt][0];
            stg[g * 50 + cc + 1] = accB[nt][1];
            stg[(g + 8) * 50 + cc] = accB[nt][2];
            stg[(g + 8) * 50 + cc + 1] = accB[nt][3];
        }
        __syncwarp();
#pragma unroll
        for (int nt = 0; nt < 4; nt++) {
            const int jl = nt * 8 + 2 * tig;
            const float bd0 = stg[g * 50 + jl - g + 15], bd1 = stg[g * 50 + jl - g + 16];
            const float bd2 = stg[(g + 8) * 50 + jl - g + 7], bd3 = stg[(g + 8) * 50 + jl - g + 8];
            const int qa = q0 + w0 + g, cc = c0 + ch * 32 + jl;
            const size_t ma = (size_t)qa * CL + cc;
            const size_t mb = (size_t)(qa + 8) * CL + cc;
            float2 mka = *(const float2*)(mask + ma);
            float2 mkb = *(const float2*)(mask + mb);
            uchar2 sga = *(const uchar2*)(segmat + ma);
            uchar2 sgb = *(const uchar2*)(segmat + mb);
            float2 oa, ob;
            oa.x = (accA[nt][0] + bd0 + (sga.x ? e1a : e0a)) * 0.125f - 1e30f * mka.x;
            oa.y = (accA[nt][1] + bd1 + (sga.y ? e1a : e0a)) * 0.125f - 1e30f * mka.y;
            ob.x = (accA[nt][2] + bd2 + (sgb.x ? e1b : e0b)) * 0.125f - 1e30f * mkb.x;
            ob.y = (accA[nt][3] + bd3 + (sgb.y ? e1b : e0b)) * 0.125f - 1e30f * mkb.y;
            *(float2*)(g_scores + ((size_t)n * QL + qa) * CL + cc) = oa;
            *(float2*)(g_scores + ((size_t)n * QL + qa + 8) * CL + cc) = ob;
        }
        __syncwarp();
    }
}

// ---------------- eseg (from split qc) ----------------
__global__ void __launch_bounds__(256) eseg_kernel(
    const float* __restrict__ cb, const float* __restrict__ sb, const float* __restrict__ seg)
{
    int idx = blockIdx.x * 256 + threadIdx.x;
    if (idx >= 2 * NH * QL) return;
    int s = idx / (NH * QL), n = (idx / QL) % NH, qi = idx % QL;
    const bf16* qh = g_qch + (long long)qi * HD + n * DH;
    const bf16* ql = g_qcl + (long long)qi * HD + n * DH;
    const float* cbr = cb + n * DH;
    const float* sbr = sb + n * DH;
    const float* sg = seg + s * (NH * DH) + n * DH;
    float acc = 0.f;
#pragma unroll
    for (int d = 0; d < DH; d++) {
        float q = __bfloat162float(qh[d]) + __bfloat162float(ql[d]) - cbr[d] + sbr[d];
        acc += q * sg[d];
    }
    g_eseg[idx] = acc;
}

// ---------------- softmax (writes split bf16 probs) ----------------
__global__ void __launch_bounds__(256) softmax_kernel()
{
    const size_t row = blockIdx.x;
    const float* p = g_scores + row * (size_t)CL;
    bf16* oh = g_ph + row * (size_t)CL;
    bf16* ol = g_pl + row * (size_t)CL;
    const int tid = threadIdx.x;
    __shared__ float red[8];
    __shared__ float sh;
    float v[8];
    float mx = -3.4e38f;
#pragma unroll
    for (int j = 0; j < 8; j++) { v[j] = p[tid + 256 * j]; mx = fmaxf(mx, v[j]); }
    mx = warpMax(mx);
    if ((tid & 31) == 0) red[tid >> 5] = mx;
    __syncthreads();
    if (tid == 0) {
        float m = red[0];
#pragma unroll
        for (int i = 1; i < 8; i++) m = fmaxf(m, red[i]);
        sh = m;
    }
    __syncthreads();
    mx = sh;
    float sum = 0.f;
#pragma unroll
    for (int j = 0; j < 8; j++) { v[j] = __expf(v[j] - mx); sum += v[j]; }
    sum = warpSum(sum);
    __syncthreads();
    if ((tid & 31) == 0) red[tid >> 5] = sum;
    __syncthreads();
    if (tid == 0) {
        float s = 0.f;
#pragma unroll
        for (int i = 0; i < 8; i++) s += red[i];
        sh = 1.0f / s;
    }
    __syncthreads();
    const float inv = sh;
#pragma unroll
    for (int j = 0; j < 8; j++) {
        bf16 h, l; splitbf(v[j] * inv, h, l);
        oh[tid + 256 * j] = h; ol[tid + 256 * j] = l;
    }
}

// ---------------- residual + LN (optional split out) ----------------
__global__ void __launch_bounds__(256) ln_kernel(
    const float* __restrict__ x, const float* __restrict__ res,
    const float* __restrict__ g, const float* __restrict__ b,
    float* __restrict__ out, bf16* __restrict__ oh, bf16* __restrict__ ol)
{
    const int row = blockIdx.x;
    __shared__ float buf[HD];
    __shared__ float red[8];
    __shared__ float s_mean, s_rstd;
    const int tid = threadIdx.x;
    float lsum = 0.f;
    for (int i = tid; i < HD; i += 256) {
        float v = x[(long long)row * HD + i] + res[(long long)row * HD + i];
        buf[i] = v; lsum += v;
    }
    lsum = warpSum(lsum);
    if ((tid & 31) == 0) red[tid >> 5] = lsum;
    __syncthreads();
    if (tid == 0) {
        float s = 0.f;
#pragma unroll
        for (int i = 0; i < 8; i++) s += red[i];
        s_mean = s * (1.0f / HD);
    }
    __syncthreads();
    const float m = s_mean;
    float lv = 0.f;
    for (int i = tid; i < HD; i += 256) { float d = buf[i] - m; lv += d * d; }
    lv = warpSum(lv);
    __syncthreads();
    if ((tid & 31) == 0) red[tid >> 5] = lv;
    __syncthreads();
    if (tid == 0) {
        float s = 0.f;
#pragma unroll
        for (int i = 0; i < 8; i++) s += red[i];
        s_rstd = rsqrtf(s * (1.0f / HD) + 1e-12f);
    }
    __syncthreads();
    const float rs = s_rstd;
    for (int i = tid; i < HD; i += 256) {
        float o = (buf[i] - m) * rs * g[i] + b[i];
        if (out) out[(long long)row * HD + i] = o;
        if (oh) { bf16 h, l; splitbf(o, h, l); oh[(long long)row * HD + i] = h; ol[(long long)row * HD + i] = l; }
    }
}

// ---------------- launch ----------------
extern "C" void kernel_launch(void* const* d_in, const int* in_sizes, int n_in,
                              void* d_out, int out_size)
{
    const float* cs = (const float*)d_in[0];
    const float* mask = (const float*)d_in[1];
    const float* ctx = (const float*)d_in[2];
    const float* pos = (const float*)d_in[3];
    const float* cb = (const float*)d_in[4];
    const float* pb = (const float*)d_in[5];
    const float* seg = (const float*)d_in[6];
    const unsigned char* segm = (const unsigned char*)d_in[7];
    const float* sbb = (const float*)d_in[8];
    const float* Wq = (const float*)d_in[9];
    const float* Wk = (const float*)d_in[10];
    const float* Wv = (const float*)d_in[11];
    const float* Wr = (const float*)d_in[12];
    const float* Wo = (const float*)d_in[13];
    const float* g1 = (const float*)d_in[14];
    const float* be1 = (const float*)d_in[15];
    const float* W1 = (const float*)d_in[16];
    const float* bf1 = (const float*)d_in[17];
    const float* W2 = (const float*)d_in[18];
    const float* bf2 = (const float*)d_in[19];
    const float* g2 = (const float*)d_in[20];
    const float* be2 = (const float*)d_in[21];
    float* out = (float*)d_out;

#define SYM(T, name, sym) T* name; cudaGetSymbolAddress((void**)&name, sym)
    SYM(float, pv, g_v); SYM(float, psc, g_scores); SYM(float, pao, g_attnout);
    SYM(float, pfi, g_ffnin); SYM(float, pfo, g_ffnout);
    SYM(bf16, csh, g_csh); SYM(bf16, csl, g_csl);
    SYM(bf16, ctxh, g_ctxh); SYM(bf16, ctxl, g_ctxl);
    SYM(bf16, posh, g_posh); SYM(bf16, posl, g_posl);
    SYM(bf16, qch, g_qch); SYM(bf16, qcl, g_qcl);
    SYM(bf16, qph, g_qph); SYM(bf16, qpl, g_qpl);
    SYM(bf16, kh, g_kh); SYM(bf16, kl, g_kl);
    SYM(bf16, rh, g_rh); SYM(bf16, rl, g_rl);
    SYM(bf16, ph, g_ph); SYM(bf16, pl, g_pl);
    SYM(bf16, ath, g_ath); SYM(bf16, atl, g_atl);
    SYM(bf16, fih, g_fih); SYM(bf16, fil, g_fil);
    SYM(bf16, fhh, g_fhh); SYM(bf16, fhl, g_fhl);
    SYM(bf16, wqh, g_wqh); SYM(bf16, wql, g_wql);
    SYM(bf16, wkh, g_wkh); SYM(bf16, wkl, g_wkl);
    SYM(bf16, wvh, g_wvh); SYM(bf16, wvl, g_wvl);
    SYM(bf16, wrh, g_wrh); SYM(bf16, wrl, g_wrl);
    SYM(bf16, woh, g_woh); SYM(bf16, wol, g_wol);
    SYM(bf16, w1h, g_w1h); SYM(bf16, w1l, g_w1l);
    SYM(bf16, w2h, g_w2h); SYM(bf16, w2l, g_w2l);
    SYM(bf16, vth, g_vth); SYM(bf16, vtl, g_vtl);
#undef SYM

    cudaFuncSetAttribute(hmma_gemm_kernel, cudaFuncAttributeMaxDynamicSharedMemorySize, GM_SMEM);
    cudaFuncSetAttribute(score_hmma_kernel, cudaFuncAttributeMaxDynamicSharedMemorySize, S_SMEM);

    dim3 blk(256);
    // input splits
    split4_kernel<<<(QL * HD / 4) / 256, blk>>>(cs, csh, csl, QL * HD / 4);
    split4_kernel<<<(CL * HD / 4) / 256, blk>>>(ctx, ctxh, ctxl, CL * HD / 4);
    split4_kernel<<<(RL * HD / 4) / 256, blk>>>(pos, posh, posl, RL * HD / 4);
    // weights
    convT_kernel<<<dim3(HD / 32, HD / 32), blk>>>(Wq, wqh, wql, HD, HD);
    convT_kernel<<<dim3(HD / 32, HD / 32), blk>>>(Wk, wkh, wkl, HD, HD);
    convT_kernel<<<dim3(HD / 32, HD / 32), blk>>>(Wv, wvh, wvl, HD, HD);
    convT_kernel<<<dim3(HD / 32, HD / 32), blk>>>(Wr, wrh, wrl, HD, HD);
    conv_kernel<<<(HD * HD) / 256, blk>>>(Wo, woh, wol, HD * HD);
    convT_kernel<<<dim3(FF / 32, HD / 32), blk>>>(W1, w1h, w1l, HD, FF);
    convT_kernel<<<dim3(HD / 32, FF / 32), blk>>>(W2, w2h, w2l, FF, HD);

    // projections (epilogue-split with per-column biases)
    hmma_gemm_kernel<<<dim3(HD / 64, QL / 128, 1), blk, GM_SMEM>>>(
        csh, csl, wqh, wql, nullptr, nullptr, qch, qcl, cb, qph, qpl, pb,
        HD, HD, HD, HD, 0, 0, 0, 0);
    hmma_gemm_kernel<<<dim3(HD / 64, CL / 128, 1), blk, GM_SMEM>>>(
        ctxh, ctxl, wkh, wkl, nullptr, nullptr, kh, kl, nullptr, nullptr, nullptr, nullptr,
        HD, HD, HD, HD, 0, 0, 0, 0);
    hmma_gemm_kernel<<<dim3(HD / 64, CL / 128, 1), blk, GM_SMEM>>>(
        ctxh, ctxl, wvh, wvl, pv, nullptr, nullptr, nullptr, nullptr, nullptr, nullptr, nullptr,
        HD, HD, HD, HD, 0, 0, 0, 0);
    hmma_gemm_kernel<<<dim3(HD / 64, RL / 128, 1), blk, GM_SMEM>>>(
        posh, posl, wrh, wrl, nullptr, nullptr, rh, rl, nullptr, nullptr, nullptr, nullptr,
        HD, HD, HD, HD, 0, 0, 0, 0);

    convT_kernel<<<dim3(HD / 32, CL / 32), blk>>>(pv, vth, vtl, CL, HD);
    eseg_kernel<<<(2 * NH * QL) / 256, blk>>>(cb, sbb, seg);

    score_hmma_kernel<<<dim3(CL / 128, QL / 128, NH), blk, S_SMEM>>>(mask, segm);
    softmax_kernel<<<NH * QL, blk>>>();

    // attn = probs @ v (per head), split out
    hmma_gemm_kernel<<<dim3(1, QL / 128, NH), blk, GM_SMEM>>>(
        ph, pl, vth, vtl, nullptr, nullptr, ath, atl, nullptr, nullptr, nullptr, nullptr,
        CL, CL, CL, HD, (long long)QL * CL, (long long)64 * CL, 64, 0);

    // attn_out = attn @ Wo^T (fp32 out)
    hmma_gemm_kernel<<<dim3(HD / 64, QL / 128, 1), blk, GM_SMEM>>>(
        ath, atl, woh, wol, pao, nullptr, nullptr, nullptr, nullptr, nullptr, nullptr, nullptr,
        HD, HD, HD, HD, 0, 0, 0, 0);

    ln_kernel<<<QL, blk>>>(pao, cs, g1, be1, pfi, fih, fil);

    hmma_gemm_kernel<<<dim3(FF / 64, QL / 128, 1), blk, GM_SMEM>>>(
        fih, fil, w1h, w1l, nullptr, nullptr, fhh, fhl, bf1, nullptr, nullptr, nullptr,
        HD, HD, HD, FF, 0, 0, 0, 1);
    hmma_gemm_kernel<<<dim3(HD / 64, QL / 128, 1), blk, GM_SMEM>>>(
        fhh, fhl, w2h, w2l, pfo, bf2, nullptr, nullptr, nullptr, nullptr, nullptr, nullptr,
        FF, FF, FF, HD, 0, 0, 0, 0);

    ln_kernel<<<QL, blk>>>(pfo, pfi, g2, be2, out, nullptr, nullptr);
}